// round 3
// baseline (speedup 1.0000x reference)
#include <cuda_runtime.h>
#include <cuda.h>
#include <cuda_bf16.h>
#include <cstdint>

// ---------------- problem constants ----------------
#define B_BATCH 64
#define S_LEN   2048
#define D_DIM   1024
#define ROWS_TOTAL (B_BATCH * S_LEN)   // 131072

// ---------------- GEMM tiling ----------------
#define TILE_M 128
#define TILE_N 256
#define KC     32
#define KITERS (D_DIM / KC)            // 32
#define NPART  4                       // D_DIM / TILE_N
#define GEMM_THREADS 512

#define A_STRIDE 36                    // floats per smem row (pad: conflict-free frags)
#define B_STRIDE 36
#define A_STAGE_B (TILE_M * A_STRIDE * 4)   // 18432 B
#define B_STAGE_B (TILE_N * B_STRIDE * 4)   // 36864 B

#define SM_W2 0
#define SM_V  1024
#define SM_E  2048                     // 4 x 128 floats
#define SM_A  4096
#define SM_B  (SM_A + 2 * A_STAGE_B)   // 40960
#define SMEM_TOTAL (SM_B + 2 * B_STAGE_B)   // 114688 B

// ---------------- scratch ----------------
__device__ float g_w1e[D_DIM * D_DIM];            // W1e rounded to tf32 (rna)
__device__ float g_v[B_BATCH * D_DIM];            // h@W1h^T + b1
__device__ float g_e_part[NPART * ROWS_TOTAL];    // per n-quarter partial e
__device__ float g_alpha[ROWS_TOTAL];
__device__ float g_ctx_part[8 * B_BATCH * D_DIM]; // split-S context partials

// ---------------- helpers ----------------
__device__ __forceinline__ uint32_t smem_u32(const void* p) {
    uint32_t a;
    asm("{ .reg .u64 t; cvta.to.shared.u64 t, %1; cvt.u32.u64 %0, t; }" : "=r"(a) : "l"(p));
    return a;
}
__device__ __forceinline__ uint32_t tf32_rna(float x) {
    uint32_t u;
    asm("cvt.rna.tf32.f32 %0, %1;" : "=r"(u) : "f"(x));
    return u;
}
__device__ __forceinline__ void cp16(uint32_t smem_addr, const void* gptr) {
    asm volatile("cp.async.cg.shared.global [%0], [%1], 16;" :: "r"(smem_addr), "l"(gptr));
}
#define CP_COMMIT() asm volatile("cp.async.commit_group;" ::: "memory")
#define CP_WAIT(n)  asm volatile("cp.async.wait_group %0;" :: "n"(n) : "memory")

__device__ __forceinline__ void mma_tf32(float* d, const uint32_t* a, const uint32_t* b) {
    asm volatile(
        "mma.sync.aligned.m16n8k8.row.col.f32.tf32.tf32.f32 "
        "{%0,%1,%2,%3}, {%4,%5,%6,%7}, {%8,%9}, {%0,%1,%2,%3};"
        : "+f"(d[0]), "+f"(d[1]), "+f"(d[2]), "+f"(d[3])
        : "r"(a[0]), "r"(a[1]), "r"(a[2]), "r"(a[3]), "r"(b[0]), "r"(b[1]));
}
__device__ __forceinline__ float tanhf_fast(float x) {
    float t;
    asm("tanh.approx.f32 %0, %1;" : "=f"(t) : "f"(x));
    return t;
}

// ---------------- kernel 1: round W1e to tf32 (rna) ----------------
__global__ void pack_w1e_kernel(const float* __restrict__ W1) {
    int idx4 = blockIdx.x * 256 + threadIdx.x;      // 262144 float4s
    int base = idx4 * 4;
    int d = base >> 10;
    int k = base & 1023;
    float4 v = *(const float4*)(W1 + (size_t)d * 2048 + k);
    v.x = __uint_as_float(tf32_rna(v.x));
    v.y = __uint_as_float(tf32_rna(v.y));
    v.z = __uint_as_float(tf32_rna(v.z));
    v.w = __uint_as_float(tf32_rna(v.w));
    *(float4*)(g_w1e + (size_t)d * 1024 + k) = v;
}

// ---------------- kernel 2: v = h @ W1h^T + b1 ----------------
__global__ void v_kernel(const float* __restrict__ hidden, const float* __restrict__ W1,
                         const float* __restrict__ b1) {
    __shared__ float hs[1024];
    int b = blockIdx.x;
    int tid = threadIdx.x, w = tid >> 5, lane = tid & 31;
    for (int i = tid; i < 1024; i += 256) hs[i] = hidden[b * 1024 + i];
    __syncthreads();
    #pragma unroll
    for (int i = 0; i < 8; i++) {
        int d = blockIdx.y * 64 + w * 8 + i;
        const float* row = W1 + (size_t)d * 2048 + 1024;
        float acc = 0.f;
        for (int m = lane; m < 1024; m += 32) acc = fmaf(hs[m], row[m], acc);
        #pragma unroll
        for (int o = 16; o; o >>= 1) acc += __shfl_xor_sync(0xFFFFFFFFu, acc, o);
        if (lane == 0) g_v[b * 1024 + d] = acc + b1[d];
    }
}

// ---------------- kernel 3: GEMM (mma.sync tf32) + tanh + W2-dot ----------------
__global__ void __launch_bounds__(GEMM_THREADS, 1)
gemm_tanh_kernel(const float* __restrict__ enc, const float* __restrict__ W2) {
    extern __shared__ char smem[];
    const int tid = threadIdx.x;
    const int wid = tid >> 5;
    const int lane = tid & 31;
    const int wm = wid & 3;           // warp m index (4)
    const int wn = wid >> 2;          // warp n index (4)
    const int qid = lane >> 2;        // 0..7
    const int qtid = lane & 3;        // 0..3
    const int d0 = blockIdx.x * TILE_N;
    const int row0 = blockIdx.y * TILE_M;
    const int b = row0 / S_LEN;

    float* W2s = (float*)(smem + SM_W2);
    float* vs  = (float*)(smem + SM_V);
    if (tid < 256) {
        W2s[tid] = W2[d0 + tid];
        vs[tid]  = g_v[b * 1024 + d0 + tid];
    }

    const uint32_t sA = smem_u32(smem + SM_A);
    const uint32_t sB = smem_u32(smem + SM_B);

    auto load_stage = [&](int stg, int kc) {
        #pragma unroll
        for (int i = 0; i < 2; i++) {               // A: 1024 x 16B
            int j = tid + i * 512;
            int r = j >> 3, seg = j & 7;
            cp16(sA + stg * A_STAGE_B + (uint32_t)(r * A_STRIDE + seg * 4) * 4,
                 enc + (size_t)(row0 + r) * 1024 + kc * 32 + seg * 4);
        }
        #pragma unroll
        for (int i = 0; i < 4; i++) {               // B: 2048 x 16B
            int j = tid + i * 512;
            int n = j >> 3, seg = j & 7;
            cp16(sB + stg * B_STAGE_B + (uint32_t)(n * B_STRIDE + seg * 4) * 4,
                 g_w1e + (size_t)(d0 + n) * 1024 + kc * 32 + seg * 4);
        }
    };

    float c[2][8][4];
    #pragma unroll
    for (int mt = 0; mt < 2; mt++)
        #pragma unroll
        for (int nt = 0; nt < 8; nt++)
            #pragma unroll
            for (int q = 0; q < 4; q++) c[mt][nt][q] = 0.f;

    load_stage(0, 0);
    CP_COMMIT();

    for (int kc = 0; kc < KITERS; kc++) {
        int cur = kc & 1;
        if (kc + 1 < KITERS) { load_stage(cur ^ 1, kc + 1); CP_COMMIT(); CP_WAIT(1); }
        else                 { CP_WAIT(0); }
        __syncthreads();

        const float* Ab = (const float*)(smem + SM_A + cur * A_STAGE_B);
        const float* Bb = (const float*)(smem + SM_B + cur * B_STAGE_B);

        #pragma unroll
        for (int ks = 0; ks < 4; ks++) {
            const int kb = ks * 8;
            uint32_t a[2][4];
            #pragma unroll
            for (int mt = 0; mt < 2; mt++) {
                int r = wm * 32 + mt * 16 + qid;
                int cc = kb + qtid;
                a[mt][0] = tf32_rna(Ab[r * A_STRIDE + cc]);
                a[mt][1] = tf32_rna(Ab[(r + 8) * A_STRIDE + cc]);
                a[mt][2] = tf32_rna(Ab[r * A_STRIDE + cc + 4]);
                a[mt][3] = tf32_rna(Ab[(r + 8) * A_STRIDE + cc + 4]);
            }
            uint32_t bf[8][2];
            #pragma unroll
            for (int nt = 0; nt < 8; nt++) {
                int n = wn * 64 + nt * 8 + qid;
                int kk = kb + qtid;
                bf[nt][0] = __float_as_uint(Bb[n * B_STRIDE + kk]);      // pre-rounded
                bf[nt][1] = __float_as_uint(Bb[n * B_STRIDE + kk + 4]);
            }
            #pragma unroll
            for (int mt = 0; mt < 2; mt++)
                #pragma unroll
                for (int nt = 0; nt < 8; nt++)
                    mma_tf32(c[mt][nt], a[mt], bf[nt]);
        }
        __syncthreads();
    }

    // ---------------- fused epilogue: e_partial = sum_n tanh(c + v[n]) * W2[n] ----------------
    float eacc[2][2] = {{0.f, 0.f}, {0.f, 0.f}};
    #pragma unroll
    for (int mt = 0; mt < 2; mt++) {
        #pragma unroll
        for (int nt = 0; nt < 8; nt++) {
            int n0 = wn * 64 + nt * 8 + 2 * qtid;
            int n1 = n0 + 1;
            float w0 = W2s[n0], w1 = W2s[n1];
            float v0 = vs[n0],  v1 = vs[n1];
            eacc[mt][0] = fmaf(tanhf_fast(c[mt][nt][0] + v0), w0, eacc[mt][0]);
            eacc[mt][0] = fmaf(tanhf_fast(c[mt][nt][1] + v1), w1, eacc[mt][0]);
            eacc[mt][1] = fmaf(tanhf_fast(c[mt][nt][2] + v0), w0, eacc[mt][1]);
            eacc[mt][1] = fmaf(tanhf_fast(c[mt][nt][3] + v1), w1, eacc[mt][1]);
        }
    }
    // reduce across the 4 lanes sharing the same rows (quad lanes qtid 0..3)
    #pragma unroll
    for (int mt = 0; mt < 2; mt++) {
        #pragma unroll
        for (int h = 0; h < 2; h++) {
            eacc[mt][h] += __shfl_xor_sync(0xFFFFFFFFu, eacc[mt][h], 1);
            eacc[mt][h] += __shfl_xor_sync(0xFFFFFFFFu, eacc[mt][h], 2);
        }
    }
    float* e_sm = (float*)(smem + SM_E);
    if (qtid == 0) {
        #pragma unroll
        for (int mt = 0; mt < 2; mt++) {
            int rloc = wm * 32 + mt * 16 + qid;
            e_sm[wn * 128 + rloc]     = eacc[mt][0];
            e_sm[wn * 128 + rloc + 8] = eacc[mt][1];
        }
    }
    __syncthreads();
    if (tid < 128) {
        float e = e_sm[tid] + e_sm[128 + tid] + e_sm[256 + tid] + e_sm[384 + tid];
        g_e_part[(size_t)blockIdx.x * ROWS_TOTAL + row0 + tid] = e;
    }
}

// ---------------- kernel 4: softmax over S per batch ----------------
__global__ void softmax_kernel() {
    __shared__ float es[S_LEN];
    __shared__ float red[256];
    int b = blockIdx.x, tid = threadIdx.x;
    float lm = -1e30f;
    for (int i = tid; i < S_LEN; i += 256) {
        int row = b * S_LEN + i;
        float e = g_e_part[row] + g_e_part[ROWS_TOTAL + row]
                + g_e_part[2 * ROWS_TOTAL + row] + g_e_part[3 * ROWS_TOTAL + row];
        es[i] = e;
        lm = fmaxf(lm, e);
    }
    red[tid] = lm; __syncthreads();
    for (int o = 128; o; o >>= 1) { if (tid < o) red[tid] = fmaxf(red[tid], red[tid + o]); __syncthreads(); }
    float mx = red[0]; __syncthreads();
    float ls = 0.f;
    for (int i = tid; i < S_LEN; i += 256) {
        float w = expf(es[i] - mx);
        es[i] = w; ls += w;
    }
    red[tid] = ls; __syncthreads();
    for (int o = 128; o; o >>= 1) { if (tid < o) red[tid] += red[tid + o]; __syncthreads(); }
    float inv = 1.f / red[0];
    for (int i = tid; i < S_LEN; i += 256) g_alpha[b * S_LEN + i] = es[i] * inv;
}

// ---------------- kernel 5: context partials (split-S) ----------------
__global__ void context_kernel(const float* __restrict__ enc) {
    __shared__ float al[256];
    int c = blockIdx.x, b = blockIdx.y, tid = threadIdx.x;
    int s0 = c * 256;
    al[tid] = g_alpha[b * S_LEN + s0 + tid];
    __syncthreads();
    float4 acc = make_float4(0.f, 0.f, 0.f, 0.f);
    const float4* base = (const float4*)(enc + ((size_t)b * S_LEN + s0) * 1024) + tid;
    #pragma unroll 4
    for (int s = 0; s < 256; s++) {
        float a = al[s];
        float4 v = base[(size_t)s * 256];
        acc.x = fmaf(a, v.x, acc.x); acc.y = fmaf(a, v.y, acc.y);
        acc.z = fmaf(a, v.z, acc.z); acc.w = fmaf(a, v.w, acc.w);
    }
    *(float4*)(g_ctx_part + ((size_t)(c * 64 + b) * 1024) + tid * 4) = acc;
}

// ---------------- kernel 6: reduce partials -> out ----------------
__global__ void reduce_kernel(float* __restrict__ out) {
    int i = blockIdx.x * 256 + threadIdx.x;   // 65536
    float s = 0.f;
    #pragma unroll
    for (int c = 0; c < 8; c++) s += g_ctx_part[(size_t)c * 65536 + i];
    out[i] = s;
}

// ---------------- launch ----------------
extern "C" void kernel_launch(void* const* d_in, const int* in_sizes, int n_in,
                              void* d_out, int out_size) {
    const float* hidden = (const float*)d_in[0];
    const float* enc    = (const float*)d_in[1];
    const float* W1     = (const float*)d_in[2];
    const float* b1     = (const float*)d_in[3];
    const float* W2     = (const float*)d_in[4];
    float* out = (float*)d_out;

    cudaFuncSetAttribute(gemm_tanh_kernel, cudaFuncAttributeMaxDynamicSharedMemorySize, SMEM_TOTAL);

    pack_w1e_kernel<<<1024, 256>>>(W1);
    v_kernel<<<dim3(64, 16), 256>>>(hidden, W1, b1);
    gemm_tanh_kernel<<<dim3(NPART, ROWS_TOTAL / TILE_M), GEMM_THREADS, SMEM_TOTAL>>>(enc, W2);
    softmax_kernel<<<64, 256>>>();
    context_kernel<<<dim3(8, 64), 256>>>(enc);
    reduce_kernel<<<256, 256>>>(out);
}